// round 6
// baseline (speedup 1.0000x reference)
#include <cuda_runtime.h>
#include <cstdint>

#define WSZ   7
#define SHF   3
#define NTOK  49
#define CDIM  96
#define NHD   3
#define HDIM  32
#define HW    112
#define NWIN  16
#define BATCH 32

// shared memory layout (float offsets)
#define XS    0        // 64 x 100 (x window, padded)
#define QS    6400     // 64 x 36
#define KS    8704     // 64 x 36
#define VS    11008    // V transposed: 32 x 68 (2176 of 2304)
#define SMS   13312    // 64 x 60 (scores / probs)
#define OS    17152    // 64 x 100 (attn out, padded)
#define BT    23552    // 507 bias table (pad to 512)
#define RSOFF 24064    // 64 ints (region ids)
#define SMEM_FLOATS (24064 + 64)
#define SMEM_BYTES  (SMEM_FLOATS * 4)

__device__ __forceinline__ uint32_t f2tf(float f) {
    uint32_t r;
    asm("cvt.rna.tf32.f32 %0, %1;" : "=r"(r) : "f"(f));
    return r;
}

__device__ __forceinline__ void mma8(float* c,
    uint32_t a0, uint32_t a1, uint32_t a2, uint32_t a3,
    uint32_t b0, uint32_t b1)
{
    asm volatile(
        "mma.sync.aligned.m16n8k8.row.col.f32.tf32.tf32.f32 "
        "{%0,%1,%2,%3},{%4,%5,%6,%7},{%8,%9},{%0,%1,%2,%3};\n"
        : "+f"(c[0]), "+f"(c[1]), "+f"(c[2]), "+f"(c[3])
        : "r"(a0), "r"(a1), "r"(a2), "r"(a3), "r"(b0), "r"(b1));
}

extern __shared__ float sm[];

__global__ void __launch_bounds__(128) swin_kernel(
    const float* __restrict__ x,
    const float* __restrict__ qkv_w,
    const float* __restrict__ qkv_b,
    const float* __restrict__ proj_w,
    const float* __restrict__ proj_b,
    const float* __restrict__ btab,
    float* __restrict__ out)
{
    const int tid = threadIdx.x;
    const int w   = tid >> 5;
    const int l   = tid & 31;
    const int g   = l >> 2;     // groupID
    const int tg  = l & 3;      // thread-in-group
    const int win = blockIdx.x;
    const int b   = win >> 8;
    const int wq  = win & 255;
    const int wy  = wq >> 4;
    const int wx  = wq & 15;
    int* rs = (int*)&sm[RSOFF];

    // ---- Phase 0: zero padded x tile, stage bias table, region ids ----
    for (int i = tid; i < 6400; i += 128) sm[XS + i] = 0.f;
    for (int i = tid; i < 507;  i += 128) sm[BT + i] = btab[i];
    if (tid < NTOK) {
        int ty = tid / 7, tx = tid - 7 * ty;
        int gy = wy * 7 + ty + SHF; if (gy >= HW) gy -= HW;
        int gx = wx * 7 + tx + SHF; if (gx >= HW) gx -= HW;
        int rh = gy < 105 ? 0 : (gy < 109 ? 1 : 2);
        int rw = gx < 105 ? 0 : (gx < 109 ? 1 : 2);
        rs[tid] = 3 * rh + rw;
    }
    __syncthreads();

    // gather shifted window: x_rolled[p] = x[(p+shift) mod HW]
    for (int i = tid; i < NTOK * CDIM; i += 128) {
        int t = i / 96, c = i - 96 * t;
        int ty = t / 7, tx = t - 7 * ty;
        int gy = wy * 7 + ty + SHF; if (gy >= HW) gy -= HW;
        int gx = wx * 7 + tx + SHF; if (gx >= HW) gx -= HW;
        sm[XS + t * 100 + c] = x[((b * HW + gy) * HW + gx) * 96 + c];
    }
    __syncthreads();

    const float SCALE = 0.17677669529663687f;  // 32^-0.5
    const int i0 = 16 * w + g;  // this warp's m-tile rows (attention phases)
    const int i1 = i0 + 8;

    for (int h = 0; h < NHD; ++h) {
        // ================= QKV (per-head chunk): [64,96] @ [96, 96cols] ====
        // warp owns local n-tiles jt = 3w..3w+2; loops all 4 m-tiles.
        float acc[4][3][4];
        #pragma unroll
        for (int mt = 0; mt < 4; mt++)
            #pragma unroll
            for (int jj = 0; jj < 3; jj++)
                #pragma unroll
                for (int q = 0; q < 4; q++) acc[mt][jj][q] = 0.f;

        const float* wb[3];
        #pragma unroll
        for (int jj = 0; jj < 3; jj++) {
            int jt = w * 3 + jj;
            int e  = jt >> 2;            // 0=q 1=k 2=v
            int d0 = (jt & 3) * 8;       // d-offset within head
            wb[jj] = qkv_w + tg * 288 + e * 96 + h * 32 + d0 + g;
        }
        #pragma unroll
        for (int k0 = 0; k0 < 96; k0 += 8) {
            uint32_t bf[3][2];
            #pragma unroll
            for (int jj = 0; jj < 3; jj++) {
                const float* p = wb[jj] + k0 * 288;
                bf[jj][0] = f2tf(p[0]);
                bf[jj][1] = f2tf(p[4 * 288]);
            }
            #pragma unroll
            for (int mt = 0; mt < 4; mt++) {
                const float* ap = &sm[XS + (16 * mt + g) * 100 + k0 + tg];
                uint32_t a0 = f2tf(ap[0]),   a1 = f2tf(ap[800]);
                uint32_t a2 = f2tf(ap[4]),   a3 = f2tf(ap[804]);
                #pragma unroll
                for (int jj = 0; jj < 3; jj++)
                    mma8(acc[mt][jj], a0, a1, a2, a3, bf[jj][0], bf[jj][1]);
            }
        }
        // epilogue: +bias, scale q, scatter to q/k/vT smem
        #pragma unroll
        for (int jj = 0; jj < 3; jj++) {
            int jt = w * 3 + jj;
            int e  = jt >> 2;
            int dl = (jt & 3) * 8 + 2 * tg;
            int gc = e * 96 + h * 32 + dl;
            float b0v = qkv_b[gc], b1v = qkv_b[gc + 1];
            #pragma unroll
            for (int mt = 0; mt < 4; mt++) {
                int r0 = 16 * mt + g, r1 = r0 + 8;
                float v00 = acc[mt][jj][0] + b0v, v01 = acc[mt][jj][1] + b1v;
                float v10 = acc[mt][jj][2] + b0v, v11 = acc[mt][jj][3] + b1v;
                if (e == 0) {
                    v00 *= SCALE; v01 *= SCALE; v10 *= SCALE; v11 *= SCALE;
                    sm[QS + r0 * 36 + dl]     = v00;
                    sm[QS + r0 * 36 + dl + 1] = v01;
                    sm[QS + r1 * 36 + dl]     = v10;
                    sm[QS + r1 * 36 + dl + 1] = v11;
                } else if (e == 1) {
                    sm[KS + r0 * 36 + dl]     = v00;
                    sm[KS + r0 * 36 + dl + 1] = v01;
                    sm[KS + r1 * 36 + dl]     = v10;
                    sm[KS + r1 * 36 + dl + 1] = v11;
                } else {  // V stored transposed [d][token], stride 68
                    sm[VS + dl * 68 + r0]       = v00;
                    sm[VS + (dl + 1) * 68 + r0] = v01;
                    sm[VS + dl * 68 + r1]       = v10;
                    sm[VS + (dl + 1) * 68 + r1] = v11;
                }
            }
        }
        __syncthreads();

        // ================= S = Q @ K^T  [64 x 56] =========================
        float sacc[7][4];
        #pragma unroll
        for (int nt = 0; nt < 7; nt++)
            #pragma unroll
            for (int q = 0; q < 4; q++) sacc[nt][q] = 0.f;
        #pragma unroll
        for (int k0 = 0; k0 < 32; k0 += 8) {
            const float* qp = &sm[QS + i0 * 36 + k0 + tg];
            uint32_t a0 = f2tf(qp[0]),  a1 = f2tf(qp[288]);
            uint32_t a2 = f2tf(qp[4]),  a3 = f2tf(qp[292]);
            #pragma unroll
            for (int nt = 0; nt < 7; nt++) {
                const float* kp = &sm[KS + (nt * 8 + g) * 36 + k0 + tg];
                mma8(sacc[nt], a0, a1, a2, a3, f2tf(kp[0]), f2tf(kp[4]));
            }
        }
        // epilogue: + rel-pos bias + shift mask, handle padding
        {
            int yi0 = i0 / 7, xi0 = i0 - 7 * yi0;
            int yi1 = i1 / 7, xi1 = i1 - 7 * yi1;
            int ri0 = (i0 < NTOK) ? rs[i0] : 0;
            int ri1 = (i1 < NTOK) ? rs[i1] : 0;
            #pragma unroll
            for (int nt = 0; nt < 7; nt++) {
                int j0 = nt * 8 + 2 * tg;
                #pragma unroll
                for (int q = 0; q < 4; q++) {
                    int i  = (q < 2) ? i0 : i1;
                    int j  = j0 + (q & 1);
                    int yi = (q < 2) ? yi0 : yi1;
                    int xi = (q < 2) ? xi0 : xi1;
                    int ri = (q < 2) ? ri0 : ri1;
                    float v;
                    if (i >= NTOK)       v = 0.f;
                    else if (j >= NTOK)  v = -1e9f;
                    else {
                        int yj = j / 7, xj = j - 7 * yj;
                        float bias = sm[BT + ((yi - yj + 6) * 13 + (xi - xj + 6)) * 3 + h];
                        float msk  = (ri != rs[j]) ? -1e9f : 0.f;
                        v = sacc[nt][q] + bias + msk;
                    }
                    sm[SMS + i * 60 + j] = v;
                }
            }
        }
        __syncthreads();

        // ================= softmax (warp per row) =========================
        for (int r = w; r < NTOK; r += 4) {
            float v0 = sm[SMS + r * 60 + l];
            float v1 = (l < 24) ? sm[SMS + r * 60 + 32 + l] : -1e30f;
            float m = fmaxf(v0, v1);
            #pragma unroll
            for (int o = 16; o > 0; o >>= 1)
                m = fmaxf(m, __shfl_xor_sync(0xffffffffu, m, o));
            float e0 = __expf(v0 - m);
            float e1 = (l < 24) ? __expf(v1 - m) : 0.f;
            float s = e0 + e1;
            #pragma unroll
            for (int o = 16; o > 0; o >>= 1)
                s += __shfl_xor_sync(0xffffffffu, s, o);
            float inv = 1.f / s;
            sm[SMS + r * 60 + l] = e0 * inv;
            if (l < 24)
                sm[SMS + r * 60 + 32 + l] = (l < 17) ? e1 * inv : 0.f;
        }
        __syncthreads();

        // ================= O_h = P @ V  [64 x 32] =========================
        float oacc[4][4];
        #pragma unroll
        for (int nt = 0; nt < 4; nt++)
            #pragma unroll
            for (int q = 0; q < 4; q++) oacc[nt][q] = 0.f;
        #pragma unroll
        for (int k0 = 0; k0 < 56; k0 += 8) {
            const float* pp = &sm[SMS + i0 * 60 + k0 + tg];
            uint32_t a0 = f2tf(pp[0]),  a1 = f2tf(pp[480]);
            uint32_t a2 = f2tf(pp[4]),  a3 = f2tf(pp[484]);
            #pragma unroll
            for (int nt = 0; nt < 4; nt++) {
                const float* vp = &sm[VS + (nt * 8 + g) * 68 + k0 + tg];
                mma8(oacc[nt], a0, a1, a2, a3, f2tf(vp[0]), f2tf(vp[4]));
            }
        }
        #pragma unroll
        for (int nt = 0; nt < 4; nt++) {
            int c = h * 32 + nt * 8 + 2 * tg;
            sm[OS + i0 * 100 + c]     = oacc[nt][0];
            sm[OS + i0 * 100 + c + 1] = oacc[nt][1];
            sm[OS + i1 * 100 + c]     = oacc[nt][2];
            sm[OS + i1 * 100 + c + 1] = oacc[nt][3];
        }
        __syncthreads();
    }  // heads

    // ================= proj: [64,96] @ [96,96] + b, scatter out ==========
    float pacc[4][3][4];
    #pragma unroll
    for (int mt = 0; mt < 4; mt++)
        #pragma unroll
        for (int jj = 0; jj < 3; jj++)
            #pragma unroll
            for (int q = 0; q < 4; q++) pacc[mt][jj][q] = 0.f;

    const float* pwb[3];
    #pragma unroll
    for (int jj = 0; jj < 3; jj++)
        pwb[jj] = proj_w + tg * 96 + (3 * w + jj) * 8 + g;

    #pragma unroll
    for (int k0 = 0; k0 < 96; k0 += 8) {
        uint32_t bf[3][2];
        #pragma unroll
        for (int jj = 0; jj < 3; jj++) {
            const float* p = pwb[jj] + k0 * 96;
            bf[jj][0] = f2tf(p[0]);
            bf[jj][1] = f2tf(p[4 * 96]);
        }
        #pragma unroll
        for (int mt = 0; mt < 4; mt++) {
            const float* ap = &sm[OS + (16 * mt + g) * 100 + k0 + tg];
            uint32_t a0 = f2tf(ap[0]),  a1 = f2tf(ap[800]);
            uint32_t a2 = f2tf(ap[4]),  a3 = f2tf(ap[804]);
            #pragma unroll
            for (int jj = 0; jj < 3; jj++)
                mma8(pacc[mt][jj], a0, a1, a2, a3, bf[jj][0], bf[jj][1]);
        }
    }
    // epilogue: +proj_b, write to rolled-back global position (same coords as load)
    #pragma unroll
    for (int mt = 0; mt < 4; mt++) {
        int r0 = 16 * mt + g, r1 = r0 + 8;
        if (r0 < NTOK) {
            int ty = r0 / 7, tx = r0 - 7 * ty;
            int gy = wy * 7 + ty + SHF; if (gy >= HW) gy -= HW;
            int gx = wx * 7 + tx + SHF; if (gx >= HW) gx -= HW;
            float* op = out + ((size_t)(b * HW + gy) * HW + gx) * 96;
            #pragma unroll
            for (int jj = 0; jj < 3; jj++) {
                int c = (3 * w + jj) * 8 + 2 * tg;
                float2 v;
                v.x = pacc[mt][jj][0] + proj_b[c];
                v.y = pacc[mt][jj][1] + proj_b[c + 1];
                *(float2*)(op + c) = v;
            }
        }
        if (r1 < NTOK) {
            int ty = r1 / 7, tx = r1 - 7 * ty;
            int gy = wy * 7 + ty + SHF; if (gy >= HW) gy -= HW;
            int gx = wx * 7 + tx + SHF; if (gx >= HW) gx -= HW;
            float* op = out + ((size_t)(b * HW + gy) * HW + gx) * 96;
            #pragma unroll
            for (int jj = 0; jj < 3; jj++) {
                int c = (3 * w + jj) * 8 + 2 * tg;
                float2 v;
                v.x = pacc[mt][jj][2] + proj_b[c];
                v.y = pacc[mt][jj][3] + proj_b[c + 1];
                *(float2*)(op + c) = v;
            }
        }
    }
}

extern "C" void kernel_launch(void* const* d_in, const int* in_sizes, int n_in,
                              void* d_out, int out_size)
{
    const float* x      = (const float*)d_in[0];
    const float* qkv_w  = (const float*)d_in[1];
    const float* qkv_b  = (const float*)d_in[2];
    const float* proj_w = (const float*)d_in[3];
    const float* proj_b = (const float*)d_in[4];
    const float* btab   = (const float*)d_in[5];
    float* out = (float*)d_out;

    cudaFuncSetAttribute(swin_kernel,
                         cudaFuncAttributeMaxDynamicSharedMemorySize,
                         SMEM_BYTES);

    const int n_windows = BATCH * NWIN * NWIN;  // 8192
    swin_kernel<<<n_windows, 128, SMEM_BYTES>>>(
        x, qkv_w, qkv_b, proj_w, proj_b, btab, out);
}

// round 8
// speedup vs baseline: 1.2348x; 1.2348x over previous
#include <cuda_runtime.h>
#include <cstdint>

#define WSZ   7
#define SHF   3
#define NTOK  49
#define HW    112
#define NWIN  16
#define BATCH 32

// shared memory layout (32-bit word offsets). All matrix tiles hold tf32 BIT
// PATTERNS (uint32) except SMS pre-softmax (raw float scores) and BT (float).
#define XS    0        // 64 x 100 (x window, tf32 bits, rows 49-63 zero)
#define QS    6400     // 64 x 36   tf32 bits
#define KS    8704     // 64 x 36   tf32 bits
#define VS    11008    // V^T 32 x 68 tf32 bits
#define SMS   13312    // 64 x 60  scores(float) -> probs(tf32 bits)
#define OH    13312    // 64 x 36  per-head attn out (tf32 bits), aliases SMS
#define BT    17152    // 507 bias table (float)
#define RSOFF 17664    // 64 ints (region ids)
#define SMEM_WORDS (17664 + 64)
#define SMEM_BYTES (SMEM_WORDS * 4)

__device__ uint32_t g_qkvw[96 * 288];   // tf32-bit copy of qkv_w
__device__ uint32_t g_projw[96 * 96];   // tf32-bit copy of proj_w

__device__ __forceinline__ uint32_t f2tf(float f) {
    uint32_t r;
    asm("cvt.rna.tf32.f32 %0, %1;" : "=r"(r) : "f"(f));
    return r;
}

__device__ __forceinline__ void mma8(float* c,
    uint32_t a0, uint32_t a1, uint32_t a2, uint32_t a3,
    uint32_t b0, uint32_t b1)
{
    asm volatile(
        "mma.sync.aligned.m16n8k8.row.col.f32.tf32.tf32.f32 "
        "{%0,%1,%2,%3},{%4,%5,%6,%7},{%8,%9},{%0,%1,%2,%3};\n"
        : "+f"(c[0]), "+f"(c[1]), "+f"(c[2]), "+f"(c[3])
        : "r"(a0), "r"(a1), "r"(a2), "r"(a3), "r"(b0), "r"(b1));
}

__global__ void __launch_bounds__(256) prep_kernel(
    const float* __restrict__ qkv_w, const float* __restrict__ proj_w)
{
    int i = blockIdx.x * 256 + threadIdx.x;
    if (i < 96 * 288) g_qkvw[i] = f2tf(qkv_w[i]);
    if (i < 96 * 96)  g_projw[i] = f2tf(proj_w[i]);
}

extern __shared__ uint32_t smu[];

__global__ void __launch_bounds__(128, 3) swin_kernel(
    const float* __restrict__ x,
    const float* __restrict__ qkv_b,
    const float* __restrict__ proj_b,
    const float* __restrict__ btab,
    float* __restrict__ out)
{
    float* sm_f = (float*)smu;
    const int tid = threadIdx.x;
    const int w   = tid >> 5;
    const int l   = tid & 31;
    const int g   = l >> 2;
    const int tg  = l & 3;
    const int win = blockIdx.x;
    const int b   = win >> 8;
    const int wq  = win & 255;
    const int wy  = wq >> 4;
    const int wx  = wq & 15;
    int* rs = (int*)&smu[RSOFF];

    // ---- Phase 0: zero padded X rows, stage bias table, region ids ----
    for (int i = tid; i < 1500; i += 128) smu[XS + 4900 + i] = 0u;   // rows 49-63
    for (int i = tid; i < 507;  i += 128) sm_f[BT + i] = btab[i];
    if (tid < NTOK) {
        int ty = tid / 7, tx = tid - 7 * ty;
        int gy = wy * 7 + ty + SHF; if (gy >= HW) gy -= HW;
        int gx = wx * 7 + tx + SHF; if (gx >= HW) gx -= HW;
        int rh = gy < 105 ? 0 : (gy < 109 ? 1 : 2);
        int rw = gx < 105 ? 0 : (gx < 109 ? 1 : 2);
        rs[tid] = 3 * rh + rw;
    }

    // gather shifted window as tf32 bits (vectorized float4)
    for (int i = tid; i < NTOK * 24; i += 128) {
        int t = i / 24, c4 = i - 24 * t;
        int ty = t / 7, tx = t - 7 * ty;
        int gy = wy * 7 + ty + SHF; if (gy >= HW) gy -= HW;
        int gx = wx * 7 + tx + SHF; if (gx >= HW) gx -= HW;
        float4 v = *(const float4*)(x + ((size_t)(b * HW + gy) * HW + gx) * 96 + c4 * 4);
        uint32_t* d = &smu[XS + t * 100 + c4 * 4];
        d[0] = f2tf(v.x); d[1] = f2tf(v.y); d[2] = f2tf(v.z); d[3] = f2tf(v.w);
    }
    __syncthreads();

    const float SCALE = 0.17677669529663687f;
    const int i0 = 16 * w + g;
    const int i1 = i0 + 8;

    // projection accumulators, live across all heads
    float pacc[4][3][4];
    #pragma unroll
    for (int mt = 0; mt < 4; mt++)
        #pragma unroll
        for (int jj = 0; jj < 3; jj++)
            #pragma unroll
            for (int q = 0; q < 4; q++) pacc[mt][jj][q] = 0.f;

    for (int h = 0; h < 3; ++h) {
        // ================= QKV (per-head chunk): [64,96] @ [96,96] ========
        float acc[4][3][4];
        #pragma unroll
        for (int mt = 0; mt < 4; mt++)
            #pragma unroll
            for (int jj = 0; jj < 3; jj++)
                #pragma unroll
                for (int q = 0; q < 4; q++) acc[mt][jj][q] = 0.f;

        const uint32_t* wb[3];
        #pragma unroll
        for (int jj = 0; jj < 3; jj++) {
            int jt = w * 3 + jj;
            int e  = jt >> 2;
            int d0 = (jt & 3) * 8;
            wb[jj] = g_qkvw + tg * 288 + e * 96 + h * 32 + d0 + g;
        }
        #pragma unroll
        for (int k0 = 0; k0 < 96; k0 += 8) {
            uint32_t bf[3][2];
            #pragma unroll
            for (int jj = 0; jj < 3; jj++) {
                const uint32_t* p = wb[jj] + k0 * 288;
                bf[jj][0] = p[0];
                bf[jj][1] = p[4 * 288];
            }
            #pragma unroll
            for (int mt = 0; mt < 4; mt++) {
                const uint32_t* ap = &smu[XS + (16 * mt + g) * 100 + k0 + tg];
                uint32_t a0 = ap[0], a1 = ap[800], a2 = ap[4], a3 = ap[804];
                #pragma unroll
                for (int jj = 0; jj < 3; jj++)
                    mma8(acc[mt][jj], a0, a1, a2, a3, bf[jj][0], bf[jj][1]);
            }
        }
        // epilogue: +bias, scale q, store tf32 bits to q/k/vT smem
        #pragma unroll
        for (int jj = 0; jj < 3; jj++) {
            int jt = w * 3 + jj;
            int e  = jt >> 2;
            int dl = (jt & 3) * 8 + 2 * tg;
            int gc = e * 96 + h * 32 + dl;
            float b0v = qkv_b[gc], b1v = qkv_b[gc + 1];
            #pragma unroll
            for (int mt = 0; mt < 4; mt++) {
                int r0 = 16 * mt + g, r1 = r0 + 8;
                float v00 = acc[mt][jj][0] + b0v, v01 = acc[mt][jj][1] + b1v;
                float v10 = acc[mt][jj][2] + b0v, v11 = acc[mt][jj][3] + b1v;
                if (e == 0) {
                    smu[QS + r0 * 36 + dl]     = f2tf(v00 * SCALE);
                    smu[QS + r0 * 36 + dl + 1] = f2tf(v01 * SCALE);
                    smu[QS + r1 * 36 + dl]     = f2tf(v10 * SCALE);
                    smu[QS + r1 * 36 + dl + 1] = f2tf(v11 * SCALE);
                } else if (e == 1) {
                    smu[KS + r0 * 36 + dl]     = f2tf(v00);
                    smu[KS + r0 * 36 + dl + 1] = f2tf(v01);
                    smu[KS + r1 * 36 + dl]     = f2tf(v10);
                    smu[KS + r1 * 36 + dl + 1] = f2tf(v11);
                } else {  // V transposed [d][token], stride 68
                    smu[VS + dl * 68 + r0]       = f2tf(v00);
                    smu[VS + (dl + 1) * 68 + r0] = f2tf(v01);
                    smu[VS + dl * 68 + r1]       = f2tf(v10);
                    smu[VS + (dl + 1) * 68 + r1] = f2tf(v11);
                }
            }
        }
        __syncthreads();

        // ================= S = Q @ K^T  [64 x 56] =========================
        float sacc[7][4];
        #pragma unroll
        for (int nt = 0; nt < 7; nt++)
            #pragma unroll
            for (int q = 0; q < 4; q++) sacc[nt][q] = 0.f;
        #pragma unroll
        for (int k0 = 0; k0 < 32; k0 += 8) {
            const uint32_t* qp = &smu[QS + i0 * 36 + k0 + tg];
            uint32_t a0 = qp[0], a1 = qp[288], a2 = qp[4], a3 = qp[292];
            #pragma unroll
            for (int nt = 0; nt < 7; nt++) {
                const uint32_t* kp = &smu[KS + (nt * 8 + g) * 36 + k0 + tg];
                mma8(sacc[nt], a0, a1, a2, a3, kp[0], kp[4]);
            }
        }
        // epilogue: + rel-pos bias + shift mask (raw float scores)
        {
            int yi0 = i0 / 7, xi0 = i0 - 7 * yi0;
            int yi1 = i1 / 7, xi1 = i1 - 7 * yi1;
            int ri0 = (i0 < NTOK) ? rs[i0] : 0;
            int ri1 = (i1 < NTOK) ? rs[i1] : 0;
            #pragma unroll
            for (int nt = 0; nt < 7; nt++) {
                int j0 = nt * 8 + 2 * tg;
                #pragma unroll
                for (int q = 0; q < 4; q++) {
                    int i  = (q < 2) ? i0 : i1;
                    int j  = j0 + (q & 1);
                    int yi = (q < 2) ? yi0 : yi1;
                    int xi = (q < 2) ? xi0 : xi1;
                    int ri = (q < 2) ? ri0 : ri1;
                    float v;
                    if (i >= NTOK)       v = 0.f;
                    else if (j >= NTOK)  v = -1e9f;
                    else {
                        int yj = j / 7, xj = j - 7 * yj;
                        float bias = sm_f[BT + ((yi - yj + 6) * 13 + (xi - xj + 6)) * 3 + h];
                        float msk  = (ri != rs[j]) ? -1e9f : 0.f;
                        v = sacc[nt][q] + bias + msk;
                    }
                    sm_f[SMS + i * 60 + j] = v;
                }
            }
        }
        __syncthreads();

        // ================= softmax (warp per row), write tf32 bits ========
        for (int r = w; r < NTOK; r += 4) {
            float v0 = sm_f[SMS + r * 60 + l];
            float v1 = (l < 24) ? sm_f[SMS + r * 60 + 32 + l] : -1e30f;
            float m = fmaxf(v0, v1);
            #pragma unroll
            for (int o = 16; o > 0; o >>= 1)
                m = fmaxf(m, __shfl_xor_sync(0xffffffffu, m, o));
            float e0 = __expf(v0 - m);
            float e1 = (l < 24) ? __expf(v1 - m) : 0.f;
            float s = e0 + e1;
            #pragma unroll
            for (int o = 16; o > 0; o >>= 1)
                s += __shfl_xor_sync(0xffffffffu, s, o);
            float inv = 1.f / s;
            smu[SMS + r * 60 + l] = f2tf(e0 * inv);
            if (l < 24)
                smu[SMS + r * 60 + 32 + l] = (l < 17) ? f2tf(e1 * inv) : 0u;
        }
        __syncthreads();

        // ================= O_h = P @ V  [64 x 32] =========================
        float oacc[4][4];
        #pragma unroll
        for (int nt = 0; nt < 4; nt++)
            #pragma unroll
            for (int q = 0; q < 4; q++) oacc[nt][q] = 0.f;
        #pragma unroll
        for (int k0 = 0; k0 < 56; k0 += 8) {
            const uint32_t* pp = &smu[SMS + i0 * 60 + k0 + tg];
            uint32_t a0 = pp[0], a1 = pp[480], a2 = pp[4], a3 = pp[484];
            #pragma unroll
            for (int nt = 0; nt < 4; nt++) {
                const uint32_t* vp = &smu[VS + (nt * 8 + g) * 68 + k0 + tg];
                mma8(oacc[nt], a0, a1, a2, a3, vp[0], vp[4]);
            }
        }
        __syncthreads();   // all warps done reading probs before OH overwrite

        #pragma unroll
        for (int nt = 0; nt < 4; nt++) {
            int c = nt * 8 + 2 * tg;
            smu[OH + i0 * 36 + c]     = f2tf(oacc[nt][0]);
            smu[OH + i0 * 36 + c + 1] = f2tf(oacc[nt][1]);
            smu[OH + i1 * 36 + c]     = f2tf(oacc[nt][2]);
            smu[OH + i1 * 36 + c + 1] = f2tf(oacc[nt][3]);
        }
        __syncthreads();

        // ======= proj partial: pacc += O_h[64,32] @ proj_w[h*32:,:96] =====
        #pragma unroll
        for (int k0 = 0; k0 < 32; k0 += 8) {
            uint32_t bf[3][2];
            #pragma unroll
            for (int jj = 0; jj < 3; jj++) {
                const uint32_t* p = g_projw + (h * 32 + k0 + tg) * 96 + (3 * w + jj) * 8 + g;
                bf[jj][0] = p[0];
                bf[jj][1] = p[4 * 96];
            }
            #pragma unroll
            for (int mt = 0; mt < 4; mt++) {
                const uint32_t* ap = &smu[OH + (16 * mt + g) * 36 + k0 + tg];
                uint32_t a0 = ap[0], a1 = ap[288], a2 = ap[4], a3 = ap[292];
                #pragma unroll
                for (int jj = 0; jj < 3; jj++)
                    mma8(pacc[mt][jj], a0, a1, a2, a3, bf[jj][0], bf[jj][1]);
            }
        }
        // no sync needed here: the next write to the OH/SMS region is the
        // S-epilogue of the next head, which is behind the QKV-epilogue sync
    }  // heads

    // ================= +proj_b, scatter to rolled-back gmem ==============
    #pragma unroll
    for (int mt = 0; mt < 4; mt++) {
        #pragma unroll
        for (int half = 0; half < 2; half++) {
            int r = 16 * mt + g + 8 * half;
            if (r < NTOK) {
                int ty = r / 7, tx = r - 7 * ty;
                int gy = wy * 7 + ty + SHF; if (gy >= HW) gy -= HW;
                int gx = wx * 7 + tx + SHF; if (gx >= HW) gx -= HW;
                float* op = out + ((size_t)(b * HW + gy) * HW + gx) * 96;
                #pragma unroll
                for (int jj = 0; jj < 3; jj++) {
                    int c = (3 * w + jj) * 8 + 2 * tg;
                    float2 v;
                    v.x = pacc[mt][jj][2 * half]     + proj_b[c];
                    v.y = pacc[mt][jj][2 * half + 1] + proj_b[c + 1];
                    *(float2*)(op + c) = v;
                }
            }
        }
    }
}

extern "C" void kernel_launch(void* const* d_in, const int* in_sizes, int n_in,
                              void* d_out, int out_size)
{
    const float* x      = (const float*)d_in[0];
    const float* qkv_w  = (const float*)d_in[1];
    const float* qkv_b  = (const float*)d_in[2];
    const float* proj_w = (const float*)d_in[3];
    const float* proj_b = (const float*)d_in[4];
    const float* btab   = (const float*)d_in[5];
    float* out = (float*)d_out;

    cudaFuncSetAttribute(swin_kernel,
                         cudaFuncAttributeMaxDynamicSharedMemorySize,
                         SMEM_BYTES);

    prep_kernel<<<108, 256>>>(qkv_w, proj_w);

    const int n_windows = BATCH * NWIN * NWIN;  // 8192
    swin_kernel<<<n_windows, 128, SMEM_BYTES>>>(
        x, qkv_b, proj_b, btab, out);
}